// round 3
// baseline (speedup 1.0000x reference)
#include <cuda_runtime.h>
#include <cuda_bf16.h>
#include <cstdint>

#define MAX_NODES 100000
#define F 128
#define SSTRIDE 136   // padded bf16 row stride: per-row bank offset of 4 -> conflict-free frags

__device__ __align__(16) float g_agg[(size_t)MAX_NODES * F];
__device__ __align__(16) float g_deg[MAX_NODES];

// ---------------------------------------------------------------------------
// K0: zero the scatter scratch (must run every replay; graph replays reuse it)
// ---------------------------------------------------------------------------
__global__ void init_kernel() {
    int stride = gridDim.x * blockDim.x;
    int i = blockIdx.x * blockDim.x + threadIdx.x;
    float4 z = make_float4(0.f, 0.f, 0.f, 0.f);
    float4* a4 = reinterpret_cast<float4*>(g_agg);
    const int NA = MAX_NODES * (F / 4);
    for (int k = i; k < NA; k += stride) a4[k] = z;
    for (int k = i; k < MAX_NODES; k += stride) g_deg[k] = 0.f;
}

// ---------------------------------------------------------------------------
// K1: scatter-add. One warp per edge: lane i handles float4 [4i,4i+4) of the
// 128-float row. Full 512B row per warp -> every touched L2 sector fully used.
// Vector red.global.add.v4.f32 (sm_90+) quarters the atomic op count.
// NOTE: edge_index arrives as int32 (JAX default x64-disabled downcasts int64).
// ---------------------------------------------------------------------------
__global__ __launch_bounds__(256) void scatter_kernel(
        const float* __restrict__ x, const int* __restrict__ ei, int E) {
    int w = (blockIdx.x * 256 + threadIdx.x) >> 5;
    int lane = threadIdx.x & 31;
    if (w >= E) return;
    int src = ei[w];        // edge_index[0][e]
    int dst = ei[E + w];    // edge_index[1][e]
    float4 v = reinterpret_cast<const float4*>(x + (size_t)dst * F)[lane];
    float* p = g_agg + (size_t)src * F + lane * 4;
    asm volatile("red.global.add.v4.f32 [%0], {%1,%2,%3,%4};"
                 :: "l"(p), "f"(v.x), "f"(v.y), "f"(v.z), "f"(v.w) : "memory");
    if (lane == 0)
        asm volatile("red.global.add.f32 [%0], %1;"
                     :: "l"(&g_deg[src]), "f"(1.0f) : "memory");
}

// ---------------------------------------------------------------------------
// K2: fused GEMM  out = (agg/deg) @ W^T + x @ B^T  via bf16x3 split mma.sync.
// Block = 128 rows x 128 cols, 8 warps (2x4), warp tile 64x32 in m16n8k16.
// ---------------------------------------------------------------------------
__device__ __forceinline__ void bsplit(float v, __nv_bfloat16* hi, __nv_bfloat16* lo) {
    __nv_bfloat16 h = __float2bfloat16(v);
    *hi = h;
    *lo = __float2bfloat16(v - __bfloat162float(h));
}

#define MMA_BF16(d, a, b)                                                     \
    asm volatile("mma.sync.aligned.m16n8k16.row.col.f32.bf16.bf16.f32 "       \
                 "{%0,%1,%2,%3}, {%4,%5,%6,%7}, {%8,%9}, {%0,%1,%2,%3};"      \
                 : "+f"((d)[0]), "+f"((d)[1]), "+f"((d)[2]), "+f"((d)[3])     \
                 : "r"((a)[0]), "r"((a)[1]), "r"((a)[2]), "r"((a)[3]),        \
                   "r"((b)[0]), "r"((b)[1]))

__global__ __launch_bounds__(256, 1) void gemm_kernel(
        const float* __restrict__ x, const float* __restrict__ Wm,
        const float* __restrict__ Bm, float* __restrict__ out, int N) {
    extern __shared__ __nv_bfloat16 smem[];
    __nv_bfloat16* sAhi = smem;
    __nv_bfloat16* sAlo = sAhi + 128 * SSTRIDE;
    __nv_bfloat16* sWhi = sAlo + 128 * SSTRIDE;
    __nv_bfloat16* sWlo = sWhi + 128 * SSTRIDE;

    const int tid = threadIdx.x;
    const int lane = tid & 31;
    const int warp = tid >> 5;
    const int wm = warp & 1;    // 2 row groups of 64
    const int wn = warp >> 1;   // 4 col groups of 32
    const int g = lane >> 2;    // mma group id (row within fragment)
    const int tg = lane & 3;    // mma thread-in-group (col pair)
    const int rowBase = blockIdx.x * 128;

    float acc[4][4][4];
#pragma unroll
    for (int a = 0; a < 4; a++)
#pragma unroll
        for (int b = 0; b < 4; b++)
#pragma unroll
            for (int c = 0; c < 4; c++) acc[a][b][c] = 0.f;

    for (int phase = 0; phase < 2; phase++) {
        const float* Asrc = (phase == 0) ? g_agg : x;
        const float* Wsrc = (phase == 0) ? Wm : Bm;
        __syncthreads();   // previous phase's fragment reads done before overwrite

        // Stage weights [j][k], split hi/lo. 128x128 fp32, 16 float4 per thread.
#pragma unroll 4
        for (int i = tid; i < 128 * 32; i += 256) {
            int r = i >> 5;
            int c4 = (i & 31) << 2;
            float4 v = reinterpret_cast<const float4*>(Wsrc)[i];
            int o = r * SSTRIDE + c4;
            bsplit(v.x, sWhi + o, sWlo + o);
            bsplit(v.y, sWhi + o + 1, sWlo + o + 1);
            bsplit(v.z, sWhi + o + 2, sWlo + o + 2);
            bsplit(v.w, sWhi + o + 3, sWlo + o + 3);
        }
        // Stage A tile (agg/deg in phase 0, x in phase 1), split hi/lo.
#pragma unroll 4
        for (int i = tid; i < 128 * 32; i += 256) {
            int r = i >> 5;
            int c4 = (i & 31) << 2;
            int gr = rowBase + r;
            float4 v = make_float4(0.f, 0.f, 0.f, 0.f);
            if (gr < N) {
                v = reinterpret_cast<const float4*>(Asrc + (size_t)gr * F)[i & 31];
                if (phase == 0) {
                    float rd = 1.0f / fmaxf(g_deg[gr], 1.0f);
                    v.x *= rd; v.y *= rd; v.z *= rd; v.w *= rd;
                }
            }
            int o = r * SSTRIDE + c4;
            bsplit(v.x, sAhi + o, sAlo + o);
            bsplit(v.y, sAhi + o + 1, sAlo + o + 1);
            bsplit(v.z, sAhi + o + 2, sAlo + o + 2);
            bsplit(v.w, sAhi + o + 3, sAlo + o + 3);
        }
        __syncthreads();

#pragma unroll
        for (int ks = 0; ks < 8; ks++) {
            uint32_t ahi[4][4], alo[4][4];
            uint32_t bhi[4][2], blo[4][2];
            const int kc = ks * 16 + tg * 2;
#pragma unroll
            for (int mt = 0; mt < 4; mt++) {
                int r0 = wm * 64 + mt * 16 + g;
                const __nv_bfloat16* p0 = sAhi + r0 * SSTRIDE + kc;
                const __nv_bfloat16* p1 = sAhi + (r0 + 8) * SSTRIDE + kc;
                ahi[mt][0] = *reinterpret_cast<const uint32_t*>(p0);
                ahi[mt][1] = *reinterpret_cast<const uint32_t*>(p1);
                ahi[mt][2] = *reinterpret_cast<const uint32_t*>(p0 + 8);
                ahi[mt][3] = *reinterpret_cast<const uint32_t*>(p1 + 8);
                const __nv_bfloat16* q0 = sAlo + r0 * SSTRIDE + kc;
                const __nv_bfloat16* q1 = sAlo + (r0 + 8) * SSTRIDE + kc;
                alo[mt][0] = *reinterpret_cast<const uint32_t*>(q0);
                alo[mt][1] = *reinterpret_cast<const uint32_t*>(q1);
                alo[mt][2] = *reinterpret_cast<const uint32_t*>(q0 + 8);
                alo[mt][3] = *reinterpret_cast<const uint32_t*>(q1 + 8);
            }
#pragma unroll
            for (int nt = 0; nt < 4; nt++) {
                int j0 = wn * 32 + nt * 8 + g;
                const __nv_bfloat16* p = sWhi + j0 * SSTRIDE + kc;
                bhi[nt][0] = *reinterpret_cast<const uint32_t*>(p);
                bhi[nt][1] = *reinterpret_cast<const uint32_t*>(p + 8);
                const __nv_bfloat16* q = sWlo + j0 * SSTRIDE + kc;
                blo[nt][0] = *reinterpret_cast<const uint32_t*>(q);
                blo[nt][1] = *reinterpret_cast<const uint32_t*>(q + 8);
            }
#pragma unroll
            for (int mt = 0; mt < 4; mt++)
#pragma unroll
                for (int nt = 0; nt < 4; nt++) {
                    MMA_BF16(acc[mt][nt], ahi[mt], bhi[nt]);  // hi*hi
                    MMA_BF16(acc[mt][nt], ahi[mt], blo[nt]);  // hi*lo
                    MMA_BF16(acc[mt][nt], alo[mt], bhi[nt]);  // lo*hi
                }
        }
    }

    // Epilogue: fp32 stores, float2 per fragment half-row.
#pragma unroll
    for (int mt = 0; mt < 4; mt++) {
        int r = rowBase + wm * 64 + mt * 16 + g;
#pragma unroll
        for (int nt = 0; nt < 4; nt++) {
            int c = wn * 32 + nt * 8 + tg * 2;
            if (r < N) {
                float2 v = make_float2(acc[mt][nt][0], acc[mt][nt][1]);
                *reinterpret_cast<float2*>(out + (size_t)r * F + c) = v;
            }
            if (r + 8 < N) {
                float2 v = make_float2(acc[mt][nt][2], acc[mt][nt][3]);
                *reinterpret_cast<float2*>(out + (size_t)(r + 8) * F + c) = v;
            }
        }
    }
}

// ---------------------------------------------------------------------------
extern "C" void kernel_launch(void* const* d_in, const int* in_sizes, int n_in,
                              void* d_out, int out_size) {
    const float* x = (const float*)d_in[0];
    const int* ei = (const int*)d_in[1];     // int32: JAX x64-disabled downcast
    const float* W = (const float*)d_in[2];
    const float* B = (const float*)d_in[3];
    float* out = (float*)d_out;

    int N = in_sizes[0] / F;   // 100000
    int E = in_sizes[1] / 2;   // 625000
    if (N > MAX_NODES) N = MAX_NODES;

    init_kernel<<<2048, 256>>>();

    int scatter_blocks = (E * 32 + 255) / 256;
    scatter_kernel<<<scatter_blocks, 256>>>(x, ei, E);

    size_t smem = (size_t)4 * 128 * SSTRIDE * sizeof(__nv_bfloat16);  // 139264 B
    cudaFuncSetAttribute(gemm_kernel, cudaFuncAttributeMaxDynamicSharedMemorySize,
                         (int)smem);
    int gemm_blocks = (N + 127) / 128;
    gemm_kernel<<<gemm_blocks, 256, smem>>>(x, W, B, out, N);
}

// round 5
// speedup vs baseline: 1.3099x; 1.3099x over previous
#include <cuda_runtime.h>
#include <cuda_bf16.h>
#include <cstdint>

#define MAX_NODES 100000
#define MAX_EDGES 625000
#define F 128
#define SSTRIDE 136   // padded bf16 row stride -> conflict-free fragment LDS
#define SCAN_B 512    // nodes per scan block

__device__ __align__(16) float g_agg[(size_t)MAX_NODES * F];
__device__ int g_cnt[MAX_NODES];
__device__ int g_base[MAX_NODES];
__device__ int g_cursor[MAX_NODES];
__device__ int g_sorted[MAX_EDGES];
__device__ int g_bsums[256];
__device__ int g_boffs[256];

// ---------------------------------------------------------------------------
// P1: zero histogram (only per-replay scratch that needs clearing)
// ---------------------------------------------------------------------------
__global__ void p1_zero(int N) {
    int i = blockIdx.x * blockDim.x + threadIdx.x;
    if (i < N) g_cnt[i] = 0;
}

// P2: histogram of src
__global__ void p2_hist(const int* __restrict__ ei, int E) {
    int e = blockIdx.x * blockDim.x + threadIdx.x;
    if (e < E) atomicAdd(&g_cnt[ei[e]], 1);
}

// P3: per-block exclusive scan (512 nodes/block), emit block sums
__global__ __launch_bounds__(SCAN_B) void p3_scan(int N) {
    __shared__ int s[SCAN_B];
    int tid = threadIdx.x;
    int i = blockIdx.x * SCAN_B + tid;
    int v = (i < N) ? g_cnt[i] : 0;
    s[tid] = v;
    __syncthreads();
#pragma unroll
    for (int off = 1; off < SCAN_B; off <<= 1) {
        int t = (tid >= off) ? s[tid - off] : 0;
        __syncthreads();
        s[tid] += t;
        __syncthreads();
    }
    if (i < N) g_base[i] = s[tid] - v;          // exclusive within block
    if (tid == SCAN_B - 1) g_bsums[blockIdx.x] = s[tid];
}

// P4: scan the block sums (single block)
__global__ __launch_bounds__(256) void p4_scan_sums(int nb) {
    __shared__ int s[256];
    int tid = threadIdx.x;
    int v = (tid < nb) ? g_bsums[tid] : 0;
    s[tid] = v;
    __syncthreads();
#pragma unroll
    for (int off = 1; off < 256; off <<= 1) {
        int t = (tid >= off) ? s[tid - off] : 0;
        __syncthreads();
        s[tid] += t;
        __syncthreads();
    }
    if (tid < nb) g_boffs[tid] = s[tid] - v;    // exclusive
}

// P5: finalize base, seed cursors
__global__ void p5_offsets(int N) {
    int i = blockIdx.x * blockDim.x + threadIdx.x;
    if (i < N) {
        int b = g_base[i] + g_boffs[i >> 9];
        g_base[i] = b;
        g_cursor[i] = b;
    }
}

// P6: bucket dst indices into CSR order
__global__ void p6_bucket(const int* __restrict__ ei, int E) {
    int e = blockIdx.x * blockDim.x + threadIdx.x;
    if (e < E) {
        int src = ei[e];
        int dst = ei[E + e];
        int pos = atomicAdd(&g_cursor[src], 1);
        g_sorted[pos] = dst;
    }
}

// ---------------------------------------------------------------------------
// P7: gather-aggregate. One warp per node: register accumulation, fused
// degree normalization, single streaming store of the agg row. No f32 atomics.
// ---------------------------------------------------------------------------
__global__ __launch_bounds__(256) void p7_gather(
        const float* __restrict__ x, int N, int E) {
    int n = (blockIdx.x * 256 + threadIdx.x) >> 5;
    int lane = threadIdx.x & 31;
    if (n >= N) return;
    int s = g_base[n];
    int eend = (n + 1 < N) ? g_base[n + 1] : E;
    int cnt = eend - s;
    const float4* x4 = reinterpret_cast<const float4*>(x);
    float4 acc = make_float4(0.f, 0.f, 0.f, 0.f);
    for (int b = 0; b < cnt; b += 32) {
        int dv = (b + lane < cnt) ? g_sorted[s + b + lane] : 0;
        int m = min(32, cnt - b);
        for (int j = 0; j < m; j++) {
            int d = __shfl_sync(0xffffffffu, dv, j);
            float4 v = x4[(size_t)d * 32 + lane];
            acc.x += v.x; acc.y += v.y; acc.z += v.z; acc.w += v.w;
        }
    }
    float rd = (cnt > 0) ? (1.0f / (float)cnt) : 1.0f;
    acc.x *= rd; acc.y *= rd; acc.z *= rd; acc.w *= rd;
    reinterpret_cast<float4*>(g_agg + (size_t)n * F)[lane] = acc;
}

// ---------------------------------------------------------------------------
// K2: fused GEMM  out = agg @ W^T + x @ B^T  via bf16x3 split mma.sync.
// Block = 128 rows x 128 cols, 8 warps (2x4), warp tile 64x32 in m16n8k16.
// (agg is pre-normalized by P7.)
// ---------------------------------------------------------------------------
__device__ __forceinline__ void bsplit(float v, __nv_bfloat16* hi, __nv_bfloat16* lo) {
    __nv_bfloat16 h = __float2bfloat16(v);
    *hi = h;
    *lo = __float2bfloat16(v - __bfloat162float(h));
}

#define MMA_BF16(d, a, b)                                                     \
    asm volatile("mma.sync.aligned.m16n8k16.row.col.f32.bf16.bf16.f32 "       \
                 "{%0,%1,%2,%3}, {%4,%5,%6,%7}, {%8,%9}, {%0,%1,%2,%3};"      \
                 : "+f"((d)[0]), "+f"((d)[1]), "+f"((d)[2]), "+f"((d)[3])     \
                 : "r"((a)[0]), "r"((a)[1]), "r"((a)[2]), "r"((a)[3]),        \
                   "r"((b)[0]), "r"((b)[1]))

__global__ __launch_bounds__(256, 1) void gemm_kernel(
        const float* __restrict__ x, const float* __restrict__ Wm,
        const float* __restrict__ Bm, float* __restrict__ out, int N) {
    extern __shared__ __nv_bfloat16 smem[];
    __nv_bfloat16* sAhi = smem;
    __nv_bfloat16* sAlo = sAhi + 128 * SSTRIDE;
    __nv_bfloat16* sWhi = sAlo + 128 * SSTRIDE;
    __nv_bfloat16* sWlo = sWhi + 128 * SSTRIDE;

    const int tid = threadIdx.x;
    const int lane = tid & 31;
    const int warp = tid >> 5;
    const int wm = warp & 1;
    const int wn = warp >> 1;
    const int g = lane >> 2;
    const int tg = lane & 3;
    const int rowBase = blockIdx.x * 128;

    float acc[4][4][4];
#pragma unroll
    for (int a = 0; a < 4; a++)
#pragma unroll
        for (int b = 0; b < 4; b++)
#pragma unroll
            for (int c = 0; c < 4; c++) acc[a][b][c] = 0.f;

    for (int phase = 0; phase < 2; phase++) {
        const float* Asrc = (phase == 0) ? g_agg : x;
        const float* Wsrc = (phase == 0) ? Wm : Bm;
        __syncthreads();

#pragma unroll 4
        for (int i = tid; i < 128 * 32; i += 256) {
            int r = i >> 5;
            int c4 = (i & 31) << 2;
            float4 v = reinterpret_cast<const float4*>(Wsrc)[i];
            int o = r * SSTRIDE + c4;
            bsplit(v.x, sWhi + o, sWlo + o);
            bsplit(v.y, sWhi + o + 1, sWlo + o + 1);
            bsplit(v.z, sWhi + o + 2, sWlo + o + 2);
            bsplit(v.w, sWhi + o + 3, sWlo + o + 3);
        }
#pragma unroll 4
        for (int i = tid; i < 128 * 32; i += 256) {
            int r = i >> 5;
            int c4 = (i & 31) << 2;
            int gr = rowBase + r;
            float4 v = make_float4(0.f, 0.f, 0.f, 0.f);
            if (gr < N)
                v = reinterpret_cast<const float4*>(Asrc + (size_t)gr * F)[i & 31];
            int o = r * SSTRIDE + c4;
            bsplit(v.x, sAhi + o, sAlo + o);
            bsplit(v.y, sAhi + o + 1, sAlo + o + 1);
            bsplit(v.z, sAhi + o + 2, sAlo + o + 2);
            bsplit(v.w, sAhi + o + 3, sAlo + o + 3);
        }
        __syncthreads();

#pragma unroll
        for (int ks = 0; ks < 8; ks++) {
            uint32_t ahi[4][4], alo[4][4];
            uint32_t bhi[4][2], blo[4][2];
            const int kc = ks * 16 + tg * 2;
#pragma unroll
            for (int mt = 0; mt < 4; mt++) {
                int r0 = wm * 64 + mt * 16 + g;
                const __nv_bfloat16* p0 = sAhi + r0 * SSTRIDE + kc;
                const __nv_bfloat16* p1 = sAhi + (r0 + 8) * SSTRIDE + kc;
                ahi[mt][0] = *reinterpret_cast<const uint32_t*>(p0);
                ahi[mt][1] = *reinterpret_cast<const uint32_t*>(p1);
                ahi[mt][2] = *reinterpret_cast<const uint32_t*>(p0 + 8);
                ahi[mt][3] = *reinterpret_cast<const uint32_t*>(p1 + 8);
                const __nv_bfloat16* q0 = sAlo + r0 * SSTRIDE + kc;
                const __nv_bfloat16* q1 = sAlo + (r0 + 8) * SSTRIDE + kc;
                alo[mt][0] = *reinterpret_cast<const uint32_t*>(q0);
                alo[mt][1] = *reinterpret_cast<const uint32_t*>(q1);
                alo[mt][2] = *reinterpret_cast<const uint32_t*>(q0 + 8);
                alo[mt][3] = *reinterpret_cast<const uint32_t*>(q1 + 8);
            }
#pragma unroll
            for (int nt = 0; nt < 4; nt++) {
                int j0 = wn * 32 + nt * 8 + g;
                const __nv_bfloat16* p = sWhi + j0 * SSTRIDE + kc;
                bhi[nt][0] = *reinterpret_cast<const uint32_t*>(p);
                bhi[nt][1] = *reinterpret_cast<const uint32_t*>(p + 8);
                const __nv_bfloat16* q = sWlo + j0 * SSTRIDE + kc;
                blo[nt][0] = *reinterpret_cast<const uint32_t*>(q);
                blo[nt][1] = *reinterpret_cast<const uint32_t*>(q + 8);
            }
#pragma unroll
            for (int mt = 0; mt < 4; mt++)
#pragma unroll
                for (int nt = 0; nt < 4; nt++) {
                    MMA_BF16(acc[mt][nt], ahi[mt], bhi[nt]);
                    MMA_BF16(acc[mt][nt], ahi[mt], blo[nt]);
                    MMA_BF16(acc[mt][nt], alo[mt], bhi[nt]);
                }
        }
    }

#pragma unroll
    for (int mt = 0; mt < 4; mt++) {
        int r = rowBase + wm * 64 + mt * 16 + g;
#pragma unroll
        for (int nt = 0; nt < 4; nt++) {
            int c = wn * 32 + nt * 8 + tg * 2;
            if (r < N) {
                float2 v = make_float2(acc[mt][nt][0], acc[mt][nt][1]);
                *reinterpret_cast<float2*>(out + (size_t)r * F + c) = v;
            }
            if (r + 8 < N) {
                float2 v = make_float2(acc[mt][nt][2], acc[mt][nt][3]);
                *reinterpret_cast<float2*>(out + (size_t)(r + 8) * F + c) = v;
            }
        }
    }
}

// ---------------------------------------------------------------------------
extern "C" void kernel_launch(void* const* d_in, const int* in_sizes, int n_in,
                              void* d_out, int out_size) {
    const float* x = (const float*)d_in[0];
    const int* ei = (const int*)d_in[1];     // int32 (JAX x64-disabled)
    const float* W = (const float*)d_in[2];
    const float* B = (const float*)d_in[3];
    float* out = (float*)d_out;

    int N = in_sizes[0] / F;   // 100000
    int E = in_sizes[1] / 2;   // 625000
    if (N > MAX_NODES) N = MAX_NODES;
    if (E > MAX_EDGES) E = MAX_EDGES;

    int nb = (N + SCAN_B - 1) / SCAN_B;      // scan blocks (196)

    p1_zero<<<(N + 255) / 256, 256>>>(N);
    p2_hist<<<(E + 255) / 256, 256>>>(ei, E);
    p3_scan<<<nb, SCAN_B>>>(N);
    p4_scan_sums<<<1, 256>>>(nb);
    p5_offsets<<<(N + 255) / 256, 256>>>(N);
    p6_bucket<<<(E + 255) / 256, 256>>>(ei, E);
    p7_gather<<<(N * 32 + 255) / 256, 256>>>(x, N, E);

    size_t smem = (size_t)4 * 128 * SSTRIDE * sizeof(__nv_bfloat16);  // 139264 B
    cudaFuncSetAttribute(gemm_kernel, cudaFuncAttributeMaxDynamicSharedMemorySize,
                         (int)smem);
    gemm_kernel<<<(N + 127) / 128, 256, smem>>>(x, W, B, out, N);
}

// round 7
// speedup vs baseline: 1.3257x; 1.0121x over previous
#include <cuda_runtime.h>
#include <cuda_bf16.h>
#include <cstdint>

#define MAX_NODES 100000
#define MAX_EDGES 625000
#define F 128
#define SSTRIDE 136   // padded bf16 row stride -> conflict-free fragment LDS
#define SCAN_B 512    // nodes per scan block

__device__ __align__(16) float g_agg[(size_t)MAX_NODES * F];
__device__ int g_cnt[MAX_NODES];
__device__ int g_base[MAX_NODES];
__device__ int g_cursor[MAX_NODES];
__device__ int g_sorted[MAX_EDGES];
__device__ int g_bsums[256];
// pre-split weight planes (hi/lo bf16), filled once per launch
__device__ __align__(16) __nv_bfloat16 g_whi[F * F];
__device__ __align__(16) __nv_bfloat16 g_wlo[F * F];
__device__ __align__(16) __nv_bfloat16 g_bhi[F * F];
__device__ __align__(16) __nv_bfloat16 g_blo[F * F];

// ---------------------------------------------------------------------------
// P1: zero histogram + pre-split W/B into bf16 hi/lo planes
// ---------------------------------------------------------------------------
__global__ void p1_zero_conv(const float* __restrict__ W,
                             const float* __restrict__ B, int N) {
    int i = blockIdx.x * blockDim.x + threadIdx.x;
    if (i < N) g_cnt[i] = 0;
    if (i < F * F) {
        float w = W[i];
        __nv_bfloat16 h = __float2bfloat16(w);
        g_whi[i] = h;
        g_wlo[i] = __float2bfloat16(w - __bfloat162float(h));
        float b = B[i];
        h = __float2bfloat16(b);
        g_bhi[i] = h;
        g_blo[i] = __float2bfloat16(b - __bfloat162float(h));
    }
}

// P2: histogram of src
__global__ void p2_hist(const int* __restrict__ ei, int E) {
    int e = blockIdx.x * blockDim.x + threadIdx.x;
    if (e < E) atomicAdd(&g_cnt[ei[e]], 1);
}

// P3: per-block exclusive scan (512 nodes/block), emit block sums
__global__ __launch_bounds__(SCAN_B) void p3_scan(int N) {
    __shared__ int s[SCAN_B];
    int tid = threadIdx.x;
    int i = blockIdx.x * SCAN_B + tid;
    int v = (i < N) ? g_cnt[i] : 0;
    s[tid] = v;
    __syncthreads();
#pragma unroll
    for (int off = 1; off < SCAN_B; off <<= 1) {
        int t = (tid >= off) ? s[tid - off] : 0;
        __syncthreads();
        s[tid] += t;
        __syncthreads();
    }
    if (i < N) g_base[i] = s[tid] - v;          // exclusive within block
    if (tid == SCAN_B - 1) g_bsums[blockIdx.x] = s[tid];
}

// P45: every block redundantly scans the block sums (cheap), applies its
// offset, seeds cursors. Replaces the serialized p4 + separate p5.
__global__ __launch_bounds__(SCAN_B) void p45_offsets(int N, int nb) {
    __shared__ int s[SCAN_B];
    int tid = threadIdx.x;
    int b = blockIdx.x;
    s[tid] = (tid < nb) ? g_bsums[tid] : 0;
    __syncthreads();
#pragma unroll
    for (int off = 1; off < SCAN_B; off <<= 1) {
        int t = (tid >= off) ? s[tid - off] : 0;
        __syncthreads();
        s[tid] += t;
        __syncthreads();
    }
    int offset = (b > 0) ? s[b - 1] : 0;        // exclusive prefix for this block
    int i = b * SCAN_B + tid;
    if (i < N) {
        int v = g_base[i] + offset;
        g_base[i] = v;
        g_cursor[i] = v;
    }
}

// P6: bucket dst indices into CSR order
__global__ void p6_bucket(const int* __restrict__ ei, int E) {
    int e = blockIdx.x * blockDim.x + threadIdx.x;
    if (e < E) {
        int src = ei[e];
        int dst = ei[E + e];
        int pos = atomicAdd(&g_cursor[src], 1);
        g_sorted[pos] = dst;
    }
}

// ---------------------------------------------------------------------------
// P7: gather-aggregate. One warp per node: register accumulation, fused
// degree normalization, single streaming store of the agg row.
// ---------------------------------------------------------------------------
__global__ __launch_bounds__(256) void p7_gather(
        const float* __restrict__ x, int N, int E) {
    int n = (blockIdx.x * 256 + threadIdx.x) >> 5;
    int lane = threadIdx.x & 31;
    if (n >= N) return;
    int s = g_base[n];
    int eend = (n + 1 < N) ? g_base[n + 1] : E;
    int cnt = eend - s;
    const float4* x4 = reinterpret_cast<const float4*>(x);
    float4 acc = make_float4(0.f, 0.f, 0.f, 0.f);
    for (int b = 0; b < cnt; b += 32) {
        int dv = (b + lane < cnt) ? g_sorted[s + b + lane] : 0;
        int m = min(32, cnt - b);
        for (int j = 0; j < m; j++) {
            int d = __shfl_sync(0xffffffffu, dv, j);
            float4 v = x4[(size_t)d * 32 + lane];
            acc.x += v.x; acc.y += v.y; acc.z += v.z; acc.w += v.w;
        }
    }
    float rd = (cnt > 0) ? (1.0f / (float)cnt) : 1.0f;
    acc.x *= rd; acc.y *= rd; acc.z *= rd; acc.w *= rd;
    reinterpret_cast<float4*>(g_agg + (size_t)n * F)[lane] = acc;
}

// ---------------------------------------------------------------------------
// K2: fused GEMM  out = agg @ W^T + x @ B^T  via bf16x3 split mma.sync.
// Weight planes pre-split in global; A tile split per CTA.
// ---------------------------------------------------------------------------
__device__ __forceinline__ void bsplit(float v, __nv_bfloat16* hi, __nv_bfloat16* lo) {
    __nv_bfloat16 h = __float2bfloat16(v);
    *hi = h;
    *lo = __float2bfloat16(v - __bfloat162float(h));
}

#define MMA_BF16(d, a, b)                                                     \
    asm volatile("mma.sync.aligned.m16n8k16.row.col.f32.bf16.bf16.f32 "       \
                 "{%0,%1,%2,%3}, {%4,%5,%6,%7}, {%8,%9}, {%0,%1,%2,%3};"      \
                 : "+f"((d)[0]), "+f"((d)[1]), "+f"((d)[2]), "+f"((d)[3])     \
                 : "r"((a)[0]), "r"((a)[1]), "r"((a)[2]), "r"((a)[3]),        \
                   "r"((b)[0]), "r"((b)[1]))

__global__ __launch_bounds__(256, 1) void gemm_kernel(
        const float* __restrict__ x, float* __restrict__ out, int N) {
    extern __shared__ __nv_bfloat16 smem[];
    __nv_bfloat16* sAhi = smem;
    __nv_bfloat16* sAlo = sAhi + 128 * SSTRIDE;
    __nv_bfloat16* sWhi = sAlo + 128 * SSTRIDE;
    __nv_bfloat16* sWlo = sWhi + 128 * SSTRIDE;

    const int tid = threadIdx.x;
    const int lane = tid & 31;
    const int warp = tid >> 5;
    const int wm = warp & 1;
    const int wn = warp >> 1;
    const int g = lane >> 2;
    const int tg = lane & 3;
    const int rowBase = blockIdx.x * 128;

    float acc[4][4][4];
#pragma unroll
    for (int a = 0; a < 4; a++)
#pragma unroll
        for (int b = 0; b < 4; b++)
#pragma unroll
            for (int c = 0; c < 4; c++) acc[a][b][c] = 0.f;

    for (int phase = 0; phase < 2; phase++) {
        const float* Asrc = (phase == 0) ? g_agg : x;
        const __nv_bfloat16* WhiSrc = (phase == 0) ? g_whi : g_bhi;
        const __nv_bfloat16* WloSrc = (phase == 0) ? g_wlo : g_blo;
        __syncthreads();

        // Stage pre-split weights: straight uint4 copies (8 bf16 each).
#pragma unroll 2
        for (int i = tid; i < 128 * 16; i += 256) {
            int r = i >> 4;
            int c8 = (i & 15) << 3;
            uint4 h = reinterpret_cast<const uint4*>(WhiSrc)[i];
            uint4 l = reinterpret_cast<const uint4*>(WloSrc)[i];
            *reinterpret_cast<uint4*>(sWhi + r * SSTRIDE + c8) = h;
            *reinterpret_cast<uint4*>(sWlo + r * SSTRIDE + c8) = l;
        }
        // Stage A tile (pre-normalized agg in phase 0, x in phase 1), split hi/lo.
#pragma unroll 4
        for (int i = tid; i < 128 * 32; i += 256) {
            int r = i >> 5;
            int c4 = (i & 31) << 2;
            int gr = rowBase + r;
            float4 v = make_float4(0.f, 0.f, 0.f, 0.f);
            if (gr < N)
                v = reinterpret_cast<const float4*>(Asrc + (size_t)gr * F)[i & 31];
            int o = r * SSTRIDE + c4;
            bsplit(v.x, sAhi + o, sAlo + o);
            bsplit(v.y, sAhi + o + 1, sAlo + o + 1);
            bsplit(v.z, sAhi + o + 2, sAlo + o + 2);
            bsplit(v.w, sAhi + o + 3, sAlo + o + 3);
        }
        __syncthreads();

#pragma unroll
        for (int ks = 0; ks < 8; ks++) {
            uint32_t ahi[4][4], alo[4][4];
            uint32_t bhi[4][2], blo[4][2];
            const int kc = ks * 16 + tg * 2;
#pragma unroll
            for (int mt = 0; mt < 4; mt++) {
                int r0 = wm * 64 + mt * 16 + g;
                const __nv_bfloat16* p0 = sAhi + r0 * SSTRIDE + kc;
                const __nv_bfloat16* p1 = sAhi + (r0 + 8) * SSTRIDE + kc;
                ahi[mt][0] = *reinterpret_cast<const uint32_t*>(p0);
                ahi[mt][1] = *reinterpret_cast<const uint32_t*>(p1);
                ahi[mt][2] = *reinterpret_cast<const uint32_t*>(p0 + 8);
                ahi[mt][3] = *reinterpret_cast<const uint32_t*>(p1 + 8);
                const __nv_bfloat16* q0 = sAlo + r0 * SSTRIDE + kc;
                const __nv_bfloat16* q1 = sAlo + (r0 + 8) * SSTRIDE + kc;
                alo[mt][0] = *reinterpret_cast<const uint32_t*>(q0);
                alo[mt][1] = *reinterpret_cast<const uint32_t*>(q1);
                alo[mt][2] = *reinterpret_cast<const uint32_t*>(q0 + 8);
                alo[mt][3] = *reinterpret_cast<const uint32_t*>(q1 + 8);
            }
#pragma unroll
            for (int nt = 0; nt < 4; nt++) {
                int j0 = wn * 32 + nt * 8 + g;
                const __nv_bfloat16* p = sWhi + j0 * SSTRIDE + kc;
                bhi[nt][0] = *reinterpret_cast<const uint32_t*>(p);
                bhi[nt][1] = *reinterpret_cast<const uint32_t*>(p + 8);
                const __nv_bfloat16* q = sWlo + j0 * SSTRIDE + kc;
                blo[nt][0] = *reinterpret_cast<const uint32_t*>(q);
                blo[nt][1] = *reinterpret_cast<const uint32_t*>(q + 8);
            }
#pragma unroll
            for (int mt = 0; mt < 4; mt++)
#pragma unroll
                for (int nt = 0; nt < 4; nt++) {
                    MMA_BF16(acc[mt][nt], ahi[mt], bhi[nt]);
                    MMA_BF16(acc[mt][nt], ahi[mt], blo[nt]);
                    MMA_BF16(acc[mt][nt], alo[mt], bhi[nt]);
                }
        }
    }

#pragma unroll
    for (int mt = 0; mt < 4; mt++) {
        int r = rowBase + wm * 64 + mt * 16 + g;
#pragma unroll
        for (int nt = 0; nt < 4; nt++) {
            int c = wn * 32 + nt * 8 + tg * 2;
            if (r < N) {
                float2 v = make_float2(acc[mt][nt][0], acc[mt][nt][1]);
                *reinterpret_cast<float2*>(out + (size_t)r * F + c) = v;
            }
            if (r + 8 < N) {
                float2 v = make_float2(acc[mt][nt][2], acc[mt][nt][3]);
                *reinterpret_cast<float2*>(out + (size_t)(r + 8) * F + c) = v;
            }
        }
    }
}

// ---------------------------------------------------------------------------
extern "C" void kernel_launch(void* const* d_in, const int* in_sizes, int n_in,
                              void* d_out, int out_size) {
    const float* x = (const float*)d_in[0];
    const int* ei = (const int*)d_in[1];     // int32 (JAX x64-disabled)
    const float* W = (const float*)d_in[2];
    const float* B = (const float*)d_in[3];
    float* out = (float*)d_out;

    int N = in_sizes[0] / F;   // 100000
    int E = in_sizes[1] / 2;   // 625000
    if (N > MAX_NODES) N = MAX_NODES;
    if (E > MAX_EDGES) E = MAX_EDGES;

    int nb = (N + SCAN_B - 1) / SCAN_B;      // scan blocks (196)

    p1_zero_conv<<<(N + 255) / 256, 256>>>(W, B, N);
    p2_hist<<<(E + 255) / 256, 256>>>(ei, E);
    p3_scan<<<nb, SCAN_B>>>(N);
    p45_offsets<<<nb, SCAN_B>>>(N, nb);
    p6_bucket<<<(E + 255) / 256, 256>>>(ei, E);
    p7_gather<<<(N * 32 + 255) / 256, 256>>>(x, N, E);

    size_t smem = (size_t)4 * 128 * SSTRIDE * sizeof(__nv_bfloat16);  // 139264 B
    cudaFuncSetAttribute(gemm_kernel, cudaFuncAttributeMaxDynamicSharedMemorySize,
                         (int)smem);
    gemm_kernel<<<(N + 127) / 128, 256, smem>>>(x, out, N);
}

// round 8
// speedup vs baseline: 1.4115x; 1.0647x over previous
#include <cuda_runtime.h>
#include <cuda_bf16.h>
#include <cstdint>

#define MAX_NODES 100000
#define MAX_EDGES 625000
#define F 128
#define SSTRIDE 136   // padded bf16 row stride -> conflict-free fragment LDS
#define SCAN_B 512    // nodes per scan block
#define MTILE 256     // gemm rows per CTA

__device__ __align__(16) float g_agg[(size_t)MAX_NODES * F];
__device__ int g_cnt[MAX_NODES];
__device__ int g_base[MAX_NODES];
__device__ int g_cursor[MAX_NODES];
__device__ int g_sorted[MAX_EDGES];
__device__ int g_bsums[256];
// pre-split weight planes (hi/lo bf16), filled once per launch
__device__ __align__(16) __nv_bfloat16 g_whi[F * F];
__device__ __align__(16) __nv_bfloat16 g_wlo[F * F];
__device__ __align__(16) __nv_bfloat16 g_bhi[F * F];
__device__ __align__(16) __nv_bfloat16 g_blo[F * F];

// ---------------------------------------------------------------------------
// P1: zero histogram + pre-split W/B into bf16 hi/lo planes
// ---------------------------------------------------------------------------
__global__ void p1_zero_conv(const float* __restrict__ W,
                             const float* __restrict__ B, int N) {
    int i = blockIdx.x * blockDim.x + threadIdx.x;
    if (i < N) g_cnt[i] = 0;
    if (i < F * F) {
        float w = W[i];
        __nv_bfloat16 h = __float2bfloat16(w);
        g_whi[i] = h;
        g_wlo[i] = __float2bfloat16(w - __bfloat162float(h));
        float b = B[i];
        h = __float2bfloat16(b);
        g_bhi[i] = h;
        g_blo[i] = __float2bfloat16(b - __bfloat162float(h));
    }
}

// P2: histogram of src
__global__ void p2_hist(const int* __restrict__ ei, int E) {
    int e = blockIdx.x * blockDim.x + threadIdx.x;
    if (e < E) atomicAdd(&g_cnt[ei[e]], 1);
}

// P3: per-block exclusive scan (512 nodes/block), emit block sums
__global__ __launch_bounds__(SCAN_B) void p3_scan(int N) {
    __shared__ int s[SCAN_B];
    int tid = threadIdx.x;
    int i = blockIdx.x * SCAN_B + tid;
    int v = (i < N) ? g_cnt[i] : 0;
    s[tid] = v;
    __syncthreads();
#pragma unroll
    for (int off = 1; off < SCAN_B; off <<= 1) {
        int t = (tid >= off) ? s[tid - off] : 0;
        __syncthreads();
        s[tid] += t;
        __syncthreads();
    }
    if (i < N) g_base[i] = s[tid] - v;          // exclusive within block
    if (tid == SCAN_B - 1) g_bsums[blockIdx.x] = s[tid];
}

// P45: every block redundantly scans the block sums, applies its offset,
// seeds cursors.
__global__ __launch_bounds__(SCAN_B) void p45_offsets(int N, int nb) {
    __shared__ int s[SCAN_B];
    int tid = threadIdx.x;
    int b = blockIdx.x;
    s[tid] = (tid < nb) ? g_bsums[tid] : 0;
    __syncthreads();
#pragma unroll
    for (int off = 1; off < SCAN_B; off <<= 1) {
        int t = (tid >= off) ? s[tid - off] : 0;
        __syncthreads();
        s[tid] += t;
        __syncthreads();
    }
    int offset = (b > 0) ? s[b - 1] : 0;
    int i = b * SCAN_B + tid;
    if (i < N) {
        int v = g_base[i] + offset;
        g_base[i] = v;
        g_cursor[i] = v;
    }
}

// P6: bucket dst indices into CSR order
__global__ void p6_bucket(const int* __restrict__ ei, int E) {
    int e = blockIdx.x * blockDim.x + threadIdx.x;
    if (e < E) {
        int src = ei[e];
        int dst = ei[E + e];
        int pos = atomicAdd(&g_cursor[src], 1);
        g_sorted[pos] = dst;
    }
}

// ---------------------------------------------------------------------------
// P7: gather-aggregate. One warp per node, 4-way unrolled gather for MLP.
// ---------------------------------------------------------------------------
__global__ __launch_bounds__(256) void p7_gather(
        const float* __restrict__ x, int N, int E) {
    int n = (blockIdx.x * 256 + threadIdx.x) >> 5;
    int lane = threadIdx.x & 31;
    if (n >= N) return;
    int s = g_base[n];
    int eend = (n + 1 < N) ? g_base[n + 1] : E;
    int cnt = eend - s;
    const float4* x4 = reinterpret_cast<const float4*>(x);
    const int* sp = g_sorted + s;
    float4 acc = make_float4(0.f, 0.f, 0.f, 0.f);
    for (int b = 0; b < cnt; b += 32) {
        int dv = (b + lane < cnt) ? sp[b + lane] : 0;
        int m = min(32, cnt - b);
        int j = 0;
        for (; j + 4 <= m; j += 4) {
            int d0 = __shfl_sync(0xffffffffu, dv, j);
            int d1 = __shfl_sync(0xffffffffu, dv, j + 1);
            int d2 = __shfl_sync(0xffffffffu, dv, j + 2);
            int d3 = __shfl_sync(0xffffffffu, dv, j + 3);
            float4 v0 = x4[(size_t)d0 * 32 + lane];
            float4 v1 = x4[(size_t)d1 * 32 + lane];
            float4 v2 = x4[(size_t)d2 * 32 + lane];
            float4 v3 = x4[(size_t)d3 * 32 + lane];
            acc.x += v0.x; acc.y += v0.y; acc.z += v0.z; acc.w += v0.w;
            acc.x += v1.x; acc.y += v1.y; acc.z += v1.z; acc.w += v1.w;
            acc.x += v2.x; acc.y += v2.y; acc.z += v2.z; acc.w += v2.w;
            acc.x += v3.x; acc.y += v3.y; acc.z += v3.z; acc.w += v3.w;
        }
        for (; j < m; j++) {
            int d = __shfl_sync(0xffffffffu, dv, j);
            float4 v = x4[(size_t)d * 32 + lane];
            acc.x += v.x; acc.y += v.y; acc.z += v.z; acc.w += v.w;
        }
    }
    float rd = (cnt > 0) ? (1.0f / (float)cnt) : 1.0f;
    acc.x *= rd; acc.y *= rd; acc.z *= rd; acc.w *= rd;
    reinterpret_cast<float4*>(g_agg + (size_t)n * F)[lane] = acc;
}

// ---------------------------------------------------------------------------
// K2: fused GEMM  out = agg @ W^T + x @ B^T  via bf16x3 split mma.sync.
// CTA tile = 256 rows x 128 cols, 8 warps (4x2), warp tile 64x64.
// ---------------------------------------------------------------------------
__device__ __forceinline__ void bsplit(float v, __nv_bfloat16* hi, __nv_bfloat16* lo) {
    __nv_bfloat16 h = __float2bfloat16(v);
    *hi = h;
    *lo = __float2bfloat16(v - __bfloat162float(h));
}

#define MMA_BF16(d, a, b)                                                     \
    asm volatile("mma.sync.aligned.m16n8k16.row.col.f32.bf16.bf16.f32 "       \
                 "{%0,%1,%2,%3}, {%4,%5,%6,%7}, {%8,%9}, {%0,%1,%2,%3};"      \
                 : "+f"((d)[0]), "+f"((d)[1]), "+f"((d)[2]), "+f"((d)[3])     \
                 : "r"((a)[0]), "r"((a)[1]), "r"((a)[2]), "r"((a)[3]),        \
                   "r"((b)[0]), "r"((b)[1]))

__global__ __launch_bounds__(256, 1) void gemm_kernel(
        const float* __restrict__ x, float* __restrict__ out, int N) {
    extern __shared__ __nv_bfloat16 smem[];
    __nv_bfloat16* sAhi = smem;                         // 256 x SSTRIDE
    __nv_bfloat16* sAlo = sAhi + MTILE * SSTRIDE;       // 256 x SSTRIDE
    __nv_bfloat16* sWhi = sAlo + MTILE * SSTRIDE;       // 128 x SSTRIDE
    __nv_bfloat16* sWlo = sWhi + 128 * SSTRIDE;         // 128 x SSTRIDE

    const int tid = threadIdx.x;
    const int lane = tid & 31;
    const int warp = tid >> 5;
    const int wm = warp & 3;    // 4 row groups of 64
    const int wn = warp >> 2;   // 2 col groups of 64
    const int g = lane >> 2;
    const int tg = lane & 3;
    const int rowBase = blockIdx.x * MTILE;

    float acc[4][8][4];
#pragma unroll
    for (int a = 0; a < 4; a++)
#pragma unroll
        for (int b = 0; b < 8; b++)
#pragma unroll
            for (int c = 0; c < 4; c++) acc[a][b][c] = 0.f;

    for (int phase = 0; phase < 2; phase++) {
        const float* Asrc = (phase == 0) ? g_agg : x;
        const __nv_bfloat16* WhiSrc = (phase == 0) ? g_whi : g_bhi;
        const __nv_bfloat16* WloSrc = (phase == 0) ? g_wlo : g_blo;
        __syncthreads();

        // Stage pre-split weights: straight uint4 copies.
#pragma unroll 2
        for (int i = tid; i < 128 * 16; i += 256) {
            int r = i >> 4;
            int c8 = (i & 15) << 3;
            uint4 h = reinterpret_cast<const uint4*>(WhiSrc)[i];
            uint4 l = reinterpret_cast<const uint4*>(WloSrc)[i];
            *reinterpret_cast<uint4*>(sWhi + r * SSTRIDE + c8) = h;
            *reinterpret_cast<uint4*>(sWlo + r * SSTRIDE + c8) = l;
        }
        // Stage A tile (256 rows), split hi/lo.
#pragma unroll 4
        for (int i = tid; i < MTILE * 32; i += 256) {
            int r = i >> 5;
            int c4 = (i & 31) << 2;
            int gr = rowBase + r;
            float4 v = make_float4(0.f, 0.f, 0.f, 0.f);
            if (gr < N)
                v = reinterpret_cast<const float4*>(Asrc + (size_t)gr * F)[i & 31];
            int o = r * SSTRIDE + c4;
            bsplit(v.x, sAhi + o, sAlo + o);
            bsplit(v.y, sAhi + o + 1, sAlo + o + 1);
            bsplit(v.z, sAhi + o + 2, sAlo + o + 2);
            bsplit(v.w, sAhi + o + 3, sAlo + o + 3);
        }
        __syncthreads();

#pragma unroll
        for (int ks = 0; ks < 8; ks++) {
            const int kc = ks * 16 + tg * 2;
            // Cache all b-frags for this ks (2 col groups x 8 n-tiles)
            uint32_t bhi[8][2], blo[8][2];
#pragma unroll
            for (int nt = 0; nt < 8; nt++) {
                int j0 = wn * 64 + nt * 8 + g;
                const __nv_bfloat16* p = sWhi + j0 * SSTRIDE + kc;
                bhi[nt][0] = *reinterpret_cast<const uint32_t*>(p);
                bhi[nt][1] = *reinterpret_cast<const uint32_t*>(p + 8);
                const __nv_bfloat16* q = sWlo + j0 * SSTRIDE + kc;
                blo[nt][0] = *reinterpret_cast<const uint32_t*>(q);
                blo[nt][1] = *reinterpret_cast<const uint32_t*>(q + 8);
            }
#pragma unroll
            for (int mt = 0; mt < 4; mt++) {
                int r0 = wm * 64 + mt * 16 + g;
                uint32_t ahi[4], alo[4];
                const __nv_bfloat16* p0 = sAhi + r0 * SSTRIDE + kc;
                const __nv_bfloat16* p1 = sAhi + (r0 + 8) * SSTRIDE + kc;
                ahi[0] = *reinterpret_cast<const uint32_t*>(p0);
                ahi[1] = *reinterpret_cast<const uint32_t*>(p1);
                ahi[2] = *reinterpret_cast<const uint32_t*>(p0 + 8);
                ahi[3] = *reinterpret_cast<const uint32_t*>(p1 + 8);
                const __nv_bfloat16* q0 = sAlo + r0 * SSTRIDE + kc;
                const __nv_bfloat16* q1 = sAlo + (r0 + 8) * SSTRIDE + kc;
                alo[0] = *reinterpret_cast<const uint32_t*>(q0);
                alo[1] = *reinterpret_cast<const uint32_t*>(q1);
                alo[2] = *reinterpret_cast<const uint32_t*>(q0 + 8);
                alo[3] = *reinterpret_cast<const uint32_t*>(q1 + 8);
#pragma unroll
                for (int nt = 0; nt < 8; nt++) {
                    MMA_BF16(acc[mt][nt], ahi, bhi[nt]);
                    MMA_BF16(acc[mt][nt], ahi, blo[nt]);
                    MMA_BF16(acc[mt][nt], alo, bhi[nt]);
                }
            }
        }
    }

#pragma unroll
    for (int mt = 0; mt < 4; mt++) {
        int r = rowBase + wm * 64 + mt * 16 + g;
#pragma unroll
        for (int nt = 0; nt < 8; nt++) {
            int c = wn * 64 + nt * 8 + tg * 2;
            if (r < N) {
                float2 v = make_float2(acc[mt][nt][0], acc[mt][nt][1]);
                *reinterpret_cast<float2*>(out + (size_t)r * F + c) = v;
            }
            if (r + 8 < N) {
                float2 v = make_float2(acc[mt][nt][2], acc[mt][nt][3]);
                *reinterpret_cast<float2*>(out + (size_t)(r + 8) * F + c) = v;
            }
        }
    }
}

// ---------------------------------------------------------------------------
extern "C" void kernel_launch(void* const* d_in, const int* in_sizes, int n_in,
                              void* d_out, int out_size) {
    const float* x = (const float*)d_in[0];
    const int* ei = (const int*)d_in[1];     // int32 (JAX x64-disabled)
    const float* W = (const float*)d_in[2];
    const float* B = (const float*)d_in[3];
    float* out = (float*)d_out;

    int N = in_sizes[0] / F;   // 100000
    int E = in_sizes[1] / 2;   // 625000
    if (N > MAX_NODES) N = MAX_NODES;
    if (E > MAX_EDGES) E = MAX_EDGES;

    int nb = (N + SCAN_B - 1) / SCAN_B;      // scan blocks (196)

    p1_zero_conv<<<(N + 255) / 256, 256>>>(W, B, N);
    p2_hist<<<(E + 255) / 256, 256>>>(ei, E);
    p3_scan<<<nb, SCAN_B>>>(N);
    p45_offsets<<<nb, SCAN_B>>>(N, nb);
    p6_bucket<<<(E + 255) / 256, 256>>>(ei, E);
    p7_gather<<<(N * 32 + 255) / 256, 256>>>(x, N, E);

    // smem: (2*256 + 2*128) rows * SSTRIDE bf16 = 208896 B
    size_t smem = (size_t)(2 * MTILE + 2 * 128) * SSTRIDE * sizeof(__nv_bfloat16);
    cudaFuncSetAttribute(gemm_kernel, cudaFuncAttributeMaxDynamicSharedMemorySize,
                         (int)smem);
    gemm_kernel<<<(N + MTILE - 1) / MTILE, 256, smem>>>(x, out, N);
}

// round 9
// speedup vs baseline: 1.4332x; 1.0154x over previous
#include <cuda_runtime.h>
#include <cuda_bf16.h>
#include <cstdint>

#define MAX_NODES 100000
#define MAX_EDGES 625000
#define F 128
#define SSTRIDE 136   // padded bf16 row stride -> conflict-free fragment LDS
#define SCAN_B 512    // nodes per scan block
#define GTILE 128     // gemm rows per tile (persistent loop)

__device__ __align__(16) float g_agg[(size_t)MAX_NODES * F];
__device__ int g_cnt[MAX_NODES];
__device__ int g_base[MAX_NODES];
__device__ int g_cursor[MAX_NODES];
__device__ int g_sorted[MAX_EDGES];
__device__ int g_bsums[256];
__device__ int g_ticket;
// pre-split weight planes (hi/lo bf16), filled once per launch
__device__ __align__(16) __nv_bfloat16 g_whi[F * F];
__device__ __align__(16) __nv_bfloat16 g_wlo[F * F];
__device__ __align__(16) __nv_bfloat16 g_bhi[F * F];
__device__ __align__(16) __nv_bfloat16 g_blo[F * F];

// ---------------------------------------------------------------------------
// P1: zero histogram + ticket + pre-split W/B into bf16 hi/lo planes
// ---------------------------------------------------------------------------
__global__ void p1_zero_conv(const float* __restrict__ W,
                             const float* __restrict__ B, int N) {
    int i = blockIdx.x * blockDim.x + threadIdx.x;
    if (i == 0) g_ticket = 0;
    if (i < N) g_cnt[i] = 0;
    if (i < F * F) {
        float w = W[i];
        __nv_bfloat16 h = __float2bfloat16(w);
        g_whi[i] = h;
        g_wlo[i] = __float2bfloat16(w - __bfloat162float(h));
        float b = B[i];
        h = __float2bfloat16(b);
        g_bhi[i] = h;
        g_blo[i] = __float2bfloat16(b - __bfloat162float(h));
    }
}

// P2: histogram of src
__global__ void p2_hist(const int* __restrict__ ei, int E) {
    int e = blockIdx.x * blockDim.x + threadIdx.x;
    if (e < E) atomicAdd(&g_cnt[ei[e]], 1);
}

// P3: per-block exclusive scan (512 nodes/block), emit block sums
__global__ __launch_bounds__(SCAN_B) void p3_scan(int N) {
    __shared__ int s[SCAN_B];
    int tid = threadIdx.x;
    int i = blockIdx.x * SCAN_B + tid;
    int v = (i < N) ? g_cnt[i] : 0;
    s[tid] = v;
    __syncthreads();
#pragma unroll
    for (int off = 1; off < SCAN_B; off <<= 1) {
        int t = (tid >= off) ? s[tid - off] : 0;
        __syncthreads();
        s[tid] += t;
        __syncthreads();
    }
    if (i < N) g_base[i] = s[tid] - v;          // exclusive within block
    if (tid == SCAN_B - 1) g_bsums[blockIdx.x] = s[tid];
}

// P45: every block redundantly scans the block sums, applies its offset,
// seeds cursors.
__global__ __launch_bounds__(SCAN_B) void p45_offsets(int N, int nb) {
    __shared__ int s[SCAN_B];
    int tid = threadIdx.x;
    int b = blockIdx.x;
    s[tid] = (tid < nb) ? g_bsums[tid] : 0;
    __syncthreads();
#pragma unroll
    for (int off = 1; off < SCAN_B; off <<= 1) {
        int t = (tid >= off) ? s[tid - off] : 0;
        __syncthreads();
        s[tid] += t;
        __syncthreads();
    }
    int offset = (b > 0) ? s[b - 1] : 0;
    int i = b * SCAN_B + tid;
    if (i < N) {
        int v = g_base[i] + offset;
        g_base[i] = v;
        g_cursor[i] = v;
    }
}

// P6: bucket dst indices into CSR order
__global__ void p6_bucket(const int* __restrict__ ei, int E) {
    int e = blockIdx.x * blockDim.x + threadIdx.x;
    if (e < E) {
        int src = ei[e];
        int dst = ei[E + e];
        int pos = atomicAdd(&g_cursor[src], 1);
        g_sorted[pos] = dst;
    }
}

// ---------------------------------------------------------------------------
// P7: gather-aggregate. One warp per node, 4-way unrolled gather for MLP.
// ---------------------------------------------------------------------------
__global__ __launch_bounds__(256) void p7_gather(
        const float* __restrict__ x, int N, int E) {
    int n = (blockIdx.x * 256 + threadIdx.x) >> 5;
    int lane = threadIdx.x & 31;
    if (n >= N) return;
    int s = g_base[n];
    int eend = (n + 1 < N) ? g_base[n + 1] : E;
    int cnt = eend - s;
    const float4* x4 = reinterpret_cast<const float4*>(x);
    const int* sp = g_sorted + s;
    float4 acc = make_float4(0.f, 0.f, 0.f, 0.f);
    for (int b = 0; b < cnt; b += 32) {
        int dv = (b + lane < cnt) ? sp[b + lane] : 0;
        int m = min(32, cnt - b);
        int j = 0;
        for (; j + 4 <= m; j += 4) {
            int d0 = __shfl_sync(0xffffffffu, dv, j);
            int d1 = __shfl_sync(0xffffffffu, dv, j + 1);
            int d2 = __shfl_sync(0xffffffffu, dv, j + 2);
            int d3 = __shfl_sync(0xffffffffu, dv, j + 3);
            float4 v0 = x4[(size_t)d0 * 32 + lane];
            float4 v1 = x4[(size_t)d1 * 32 + lane];
            float4 v2 = x4[(size_t)d2 * 32 + lane];
            float4 v3 = x4[(size_t)d3 * 32 + lane];
            acc.x += v0.x; acc.y += v0.y; acc.z += v0.z; acc.w += v0.w;
            acc.x += v1.x; acc.y += v1.y; acc.z += v1.z; acc.w += v1.w;
            acc.x += v2.x; acc.y += v2.y; acc.z += v2.z; acc.w += v2.w;
            acc.x += v3.x; acc.y += v3.y; acc.z += v3.z; acc.w += v3.w;
        }
        for (; j < m; j++) {
            int d = __shfl_sync(0xffffffffu, dv, j);
            float4 v = x4[(size_t)d * 32 + lane];
            acc.x += v.x; acc.y += v.y; acc.z += v.z; acc.w += v.w;
        }
    }
    float rd = (cnt > 0) ? (1.0f / (float)cnt) : 1.0f;
    acc.x *= rd; acc.y *= rd; acc.z *= rd; acc.w *= rd;
    reinterpret_cast<float4*>(g_agg + (size_t)n * F)[lane] = acc;
}

// ---------------------------------------------------------------------------
// K2: PERSISTENT fused GEMM  out = agg @ W^T + x @ B^T  (bf16x3 mma.sync).
// 152 CTAs; weights (4 planes) staged once per CTA; dynamic tile ticket.
// Per 128-row tile: stage agg planes -> mma(W) -> stage x planes -> mma(B).
// 8 warps, warp tile 32 rows x 64 cols.
// ---------------------------------------------------------------------------
__device__ __forceinline__ void bsplit(float v, __nv_bfloat16* hi, __nv_bfloat16* lo) {
    __nv_bfloat16 h = __float2bfloat16(v);
    *hi = h;
    *lo = __float2bfloat16(v - __bfloat162float(h));
}

#define MMA_BF16(d, a, b)                                                     \
    asm volatile("mma.sync.aligned.m16n8k16.row.col.f32.bf16.bf16.f32 "       \
                 "{%0,%1,%2,%3}, {%4,%5,%6,%7}, {%8,%9}, {%0,%1,%2,%3};"      \
                 : "+f"((d)[0]), "+f"((d)[1]), "+f"((d)[2]), "+f"((d)[3])     \
                 : "r"((a)[0]), "r"((a)[1]), "r"((a)[2]), "r"((a)[3]),        \
                   "r"((b)[0]), "r"((b)[1]))

__global__ __launch_bounds__(256, 1) void gemm_persist(
        const float* __restrict__ x, float* __restrict__ out,
        int N, int ntiles) {
    extern __shared__ __nv_bfloat16 smem[];
    __nv_bfloat16* sWhi = smem;                       // phase0 weights hi
    __nv_bfloat16* sWlo = sWhi + 128 * SSTRIDE;
    __nv_bfloat16* sBhi = sWlo + 128 * SSTRIDE;       // phase1 weights hi
    __nv_bfloat16* sBlo = sBhi + 128 * SSTRIDE;
    __nv_bfloat16* sAhi = sBlo + 128 * SSTRIDE;       // A tile (reused per phase)
    __nv_bfloat16* sAlo = sAhi + 128 * SSTRIDE;
    __shared__ int s_tile;

    const int tid = threadIdx.x;
    const int lane = tid & 31;
    const int warp = tid >> 5;
    const int wm = warp & 3;    // 4 row groups of 32
    const int wn = warp >> 2;   // 2 col groups of 64
    const int g = lane >> 2;
    const int tg = lane & 3;

    // Stage all 4 weight planes ONCE per CTA.
#pragma unroll 4
    for (int i = tid; i < 128 * 16; i += 256) {
        int r = i >> 4;
        int c8 = (i & 15) << 3;
        *reinterpret_cast<uint4*>(sWhi + r * SSTRIDE + c8) =
            reinterpret_cast<const uint4*>(g_whi)[i];
        *reinterpret_cast<uint4*>(sWlo + r * SSTRIDE + c8) =
            reinterpret_cast<const uint4*>(g_wlo)[i];
        *reinterpret_cast<uint4*>(sBhi + r * SSTRIDE + c8) =
            reinterpret_cast<const uint4*>(g_bhi)[i];
        *reinterpret_cast<uint4*>(sBlo + r * SSTRIDE + c8) =
            reinterpret_cast<const uint4*>(g_blo)[i];
    }

    while (true) {
        __syncthreads();   // prior tile's LDS reads done; s_tile safe to overwrite
        if (tid == 0) s_tile = atomicAdd(&g_ticket, 1);
        __syncthreads();
        int tile = s_tile;
        if (tile >= ntiles) break;
        int rowBase = tile * GTILE;

        float acc[2][8][4];
#pragma unroll
        for (int a = 0; a < 2; a++)
#pragma unroll
            for (int b = 0; b < 8; b++)
#pragma unroll
                for (int c = 0; c < 4; c++) acc[a][b][c] = 0.f;

        for (int phase = 0; phase < 2; phase++) {
            const float* Asrc = (phase == 0) ? g_agg : x;
            const __nv_bfloat16* wh = (phase == 0) ? sWhi : sBhi;
            const __nv_bfloat16* wl = (phase == 0) ? sWlo : sBlo;
            if (phase == 1) __syncthreads();   // phase-0 reads done before restage

            // Stage A tile (128 rows), split hi/lo.
#pragma unroll 4
            for (int i = tid; i < GTILE * 32; i += 256) {
                int r = i >> 5;
                int c4 = (i & 31) << 2;
                int gr = rowBase + r;
                float4 v = make_float4(0.f, 0.f, 0.f, 0.f);
                if (gr < N)
                    v = reinterpret_cast<const float4*>(Asrc + (size_t)gr * F)[i & 31];
                int o = r * SSTRIDE + c4;
                bsplit(v.x, sAhi + o, sAlo + o);
                bsplit(v.y, sAhi + o + 1, sAlo + o + 1);
                bsplit(v.z, sAhi + o + 2, sAlo + o + 2);
                bsplit(v.w, sAhi + o + 3, sAlo + o + 3);
            }
            __syncthreads();

#pragma unroll
            for (int ks = 0; ks < 8; ks++) {
                const int kc = ks * 16 + tg * 2;
                uint32_t bhi[8][2], blo[8][2];
#pragma unroll
                for (int nt = 0; nt < 8; nt++) {
                    int j0 = wn * 64 + nt * 8 + g;
                    const __nv_bfloat16* p = wh + j0 * SSTRIDE + kc;
                    bhi[nt][0] = *reinterpret_cast<const uint32_t*>(p);
                    bhi[nt][1] = *reinterpret_cast<const uint32_t*>(p + 8);
                    const __nv_bfloat16* q = wl + j0 * SSTRIDE + kc;
                    blo[nt][0] = *reinterpret_cast<const uint32_t*>(q);
                    blo[nt][1] = *reinterpret_cast<const uint32_t*>(q + 8);
                }
#pragma unroll
                for (int mt = 0; mt < 2; mt++) {
                    int r0 = wm * 32 + mt * 16 + g;
                    uint32_t ahi[4], alo[4];
                    const __nv_bfloat16* p0 = sAhi + r0 * SSTRIDE + kc;
                    const __nv_bfloat16* p1 = sAhi + (r0 + 8) * SSTRIDE + kc;
                    ahi[0] = *reinterpret_cast<const uint32_t*>(p0);
                    ahi[1] = *reinterpret_cast<const uint32_t*>(p1);
                    ahi[2] = *reinterpret_cast<const uint32_t*>(p0 + 8);
                    ahi[3] = *reinterpret_cast<const uint32_t*>(p1 + 8);
                    const __nv_bfloat16* q0 = sAlo + r0 * SSTRIDE + kc;
                    const __nv_bfloat16* q1 = sAlo + (r0 + 8) * SSTRIDE + kc;
                    alo[0] = *reinterpret_cast<const uint32_t*>(q0);
                    alo[1] = *reinterpret_cast<const uint32_t*>(q1);
                    alo[2] = *reinterpret_cast<const uint32_t*>(q0 + 8);
                    alo[3] = *reinterpret_cast<const uint32_t*>(q1 + 8);
#pragma unroll
                    for (int nt = 0; nt < 8; nt++) {
                        MMA_BF16(acc[mt][nt], ahi, bhi[nt]);
                        MMA_BF16(acc[mt][nt], ahi, blo[nt]);
                        MMA_BF16(acc[mt][nt], alo, bhi[nt]);
                    }
                }
            }
        }

        // Epilogue
#pragma unroll
        for (int mt = 0; mt < 2; mt++) {
            int r = rowBase + wm * 32 + mt * 16 + g;
#pragma unroll
            for (int nt = 0; nt < 8; nt++) {
                int c = wn * 64 + nt * 8 + tg * 2;
                if (r < N) {
                    float2 v = make_float2(acc[mt][nt][0], acc[mt][nt][1]);
                    *reinterpret_cast<float2*>(out + (size_t)r * F + c) = v;
                }
                if (r + 8 < N) {
                    float2 v = make_float2(acc[mt][nt][2], acc[mt][nt][3]);
                    *reinterpret_cast<float2*>(out + (size_t)(r + 8) * F + c) = v;
                }
            }
        }
    }
}

// ---------------------------------------------------------------------------
extern "C" void kernel_launch(void* const* d_in, const int* in_sizes, int n_in,
                              void* d_out, int out_size) {
    const float* x = (const float*)d_in[0];
    const int* ei = (const int*)d_in[1];     // int32 (JAX x64-disabled)
    const float* W = (const float*)d_in[2];
    const float* B = (const float*)d_in[3];
    float* out = (float*)d_out;

    int N = in_sizes[0] / F;   // 100000
    int E = in_sizes[1] / 2;   // 625000
    if (N > MAX_NODES) N = MAX_NODES;
    if (E > MAX_EDGES) E = MAX_EDGES;

    int nb = (N + SCAN_B - 1) / SCAN_B;      // scan blocks (196)

    p1_zero_conv<<<(N + 255) / 256, 256>>>(W, B, N);
    p2_hist<<<(E + 255) / 256, 256>>>(ei, E);
    p3_scan<<<nb, SCAN_B>>>(N);
    p45_offsets<<<nb, SCAN_B>>>(N, nb);
    p6_bucket<<<(E + 255) / 256, 256>>>(ei, E);
    p7_gather<<<(N * 32 + 255) / 256, 256>>>(x, N, E);

    // smem: 6 planes * 128 rows * SSTRIDE bf16 = 208896 B
    size_t smem = (size_t)6 * 128 * SSTRIDE * sizeof(__nv_bfloat16);
    cudaFuncSetAttribute(gemm_persist, cudaFuncAttributeMaxDynamicSharedMemorySize,
                         (int)smem);
    int ntiles = (N + GTILE - 1) / GTILE;
    gemm_persist<<<152, 256, smem>>>(x, out, N, ntiles);
}